// round 5
// baseline (speedup 1.0000x reference)
#include <cuda_runtime.h>
#include <cuda_fp16.h>
#include <cstdint>

// Problem constants
constexpr int Bn   = 2;      // batch
constexpr int Cn   = 200;    // channels
constexpr int D3   = 16, H3 = 60, W3 = 80;     // 3D volume dims
constexpr int H2   = 120, W2 = 160;            // 2D image dims
constexpr int SX   = 60, SY = 36, SZ = 60;     // scene
constexpr int NV   = SX * SY * SZ;             // 129600 voxels per batch
constexpr int CELL3 = D3 * H3 * W3;            // 76800
constexpr int CELL2 = H2 * W2;                 // 19200
constexpr int T3   = CELL3 / 128;              // 600 transpose tiles (3D)
constexpr int T2   = CELL2 / 128;              // 150 transpose tiles (2D)

// Scratch: channel-last, pre-summed, fp16, PACKED 400B rows (all 200 ch).
// S3h[b][cell][200], S2h[b][cell][200]. Total 76.8 MB -> fits in L2.
__device__ __half S3h[(size_t)Bn * CELL3 * Cn];   // 61.4 MB
__device__ __half S2h[(size_t)Bn * CELL2 * Cn];   // 15.4 MB

// ---------------------------------------------------------------------------
// Pass 1 (fused 3D+2D): sum a+b, fp16-convert, transpose channels innermost.
// Tile = 128 cells x 200 channels. Reads float4 (512B bursts per channel),
// writes fully contiguous 51.2KB per block.
// ---------------------------------------------------------------------------
__global__ void __launch_bounds__(256) transpose_sum_kernel(
    const float4* __restrict__ x3a, const float4* __restrict__ x3b,
    const float4* __restrict__ x2a, const float4* __restrict__ x2b)
{
    __shared__ uint16_t tile[128][210];   // pad 210: 4-way STS conflict max, 32b-aligned reads
    const int bx   = blockIdx.x;
    const int bb   = blockIdx.y;
    const int lane = threadIdx.x & 31;
    const int w    = threadIdx.x >> 5;    // 8 warps

    const float4 *a, *b;
    __half* dst;
    int ncell, cell0;
    if (bx < T3) { a = x3a; b = x3b; dst = S3h; ncell = CELL3; cell0 = bx * 128; }
    else         { a = x2a; b = x2b; dst = S2h; ncell = CELL2; cell0 = (bx - T3) * 128; }

    const size_t cq   = (size_t)(ncell / 4);
    const size_t base = (size_t)bb * Cn * cq + (size_t)(cell0 / 4) + lane;

    for (int c = w; c < Cn; c += 8) {
        size_t ia = base + (size_t)c * cq;
        float4 va = __ldg(a + ia);
        float4 vb = __ldg(b + ia);
        int cell = lane * 4;
        tile[cell + 0][c] = __half_as_ushort(__float2half_rn(va.x + vb.x));
        tile[cell + 1][c] = __half_as_ushort(__float2half_rn(va.y + vb.y));
        tile[cell + 2][c] = __half_as_ushort(__float2half_rn(va.z + vb.z));
        tile[cell + 3][c] = __half_as_ushort(__float2half_rn(va.w + vb.w));
    }
    __syncthreads();

    const uint32_t* t32 = reinterpret_cast<const uint32_t*>(&tile[0][0]); // row = 105 words
    __half* outp = dst + ((size_t)bb * ncell + cell0) * Cn;
    for (int e = threadIdx.x; e < 128 * 50; e += 256) {
        int cell = e / 50;
        int q    = e - cell * 50;
        uint2 v;
        v.x = t32[cell * 105 + 2 * q];
        v.y = t32[cell * 105 + 2 * q + 1];
        *reinterpret_cast<uint2*>(outp + (size_t)cell * Cn + 4 * q) = v;   // 8B aligned: 400B rows
    }
}

// ---------------------------------------------------------------------------
// Pass 2: main gather. One warp per voxel, single pass over ALL 200 channels:
// 25 active lanes x uint4 (8 fp16 ch). 12 taps x 400B (13 sectors each).
// f32x2 packed accumulate. Output staged via smem, z-contiguous stores.
// ---------------------------------------------------------------------------
__device__ __forceinline__ uint64_t pack2(float v) {
    uint64_t r;
    asm("mov.b64 %0, {%1, %1};" : "=l"(r) : "f"(v));
    return r;
}
__device__ __forceinline__ uint64_t packf2(float2 f) {
    uint64_t r;
    asm("mov.b64 %0, {%1, %2};" : "=l"(r) : "f"(f.x), "f"(f.y));
    return r;
}
__device__ __forceinline__ void fma2(uint64_t& acc, uint64_t a, uint64_t w) {
    asm("fma.rn.f32x2 %0, %1, %2, %0;" : "+l"(acc) : "l"(a), "l"(w));
}
__device__ __forceinline__ void fma_tap(uint64_t* acc, uint4 t, uint64_t w2) {
    fma2(acc[0], packf2(__half22float2(*reinterpret_cast<__half2*>(&t.x))), w2);
    fma2(acc[1], packf2(__half22float2(*reinterpret_cast<__half2*>(&t.y))), w2);
    fma2(acc[2], packf2(__half22float2(*reinterpret_cast<__half2*>(&t.z))), w2);
    fma2(acc[3], packf2(__half22float2(*reinterpret_cast<__half2*>(&t.w))), w2);
}

__global__ void __launch_bounds__(256) flosp_kernel(
    const float* __restrict__ pp, float* __restrict__ out)
{
    __shared__ float stage[60 * 209];     // [z][209], odd stride -> conflict-free cols
    const int tid  = threadIdx.x;
    const int lane = tid & 31;
    const int w    = tid >> 5;            // 8 warps, each up to 8 z's
    const int yy   = blockIdx.x % SY;
    const int xx   = blockIdx.x / SY;
    const int bb   = blockIdx.y;

    const uint4* __restrict__ s3 =
        reinterpret_cast<const uint4*>(S3h) + (size_t)bb * CELL3 * 25;   // 25 uint4 per row
    const uint4* __restrict__ s2 =
        reinterpret_cast<const uint4*>(S2h) + (size_t)bb * CELL2 * 25;
    const float* pprow = pp + (size_t)bb * NV * 3;
    const bool active = lane < 25;

    for (int i = 0; i < 8; i++) {
        int z = w * 8 + i;
        if (z >= 60) break;
        int vox = (xx * SZ + z) * SY + yy;
        const float* p = pprow + (size_t)vox * 3;
        float p0 = __ldg(p + 0), p1 = __ldg(p + 1), p2 = __ldg(p + 2);

        // 3D coords (grid in [-1,1) -> all taps in-bounds; clamp == ref mask)
        float gx = (p0 + 1.f) * (0.5f * (W3 - 1));
        float gy = (p1 + 1.f) * (0.5f * (H3 - 1));
        float gz = (p2 + 1.f) * (0.5f * (D3 - 1));
        int ix = min(max((int)floorf(gx), 0), W3 - 2);
        int iy = min(max((int)floorf(gy), 0), H3 - 2);
        int iz = min(max((int)floorf(gz), 0), D3 - 2);
        float fx = gx - (float)ix, fy = gy - (float)iy, fz = gz - (float)iz;
        // 2D coords
        float gu = (p0 + 1.f) * (0.5f * (W2 - 1));
        float gv = (p1 + 1.f) * (0.5f * (H2 - 1));
        int iu = min(max((int)floorf(gu), 0), W2 - 2);
        int iv = min(max((int)floorf(gv), 0), H2 - 2);
        float fu = gu - (float)iu, fv = gv - (float)iv;

        if (active) {
            // row strides in uint4 units (row = 25 uint4 = 400B):
            // 3D: dx=25, dy=80*25=2000, dz=60*80*25=120000; 2D: du=25, dv=160*25=4000
            const uint4* b3 = s3 + (size_t)((iz * H3 + iy) * W3 + ix) * 25 + lane;
            const uint4* b2 = s2 + (size_t)(iv * W2 + iu) * 25 + lane;

            uint4 t000 = __ldg(b3);
            uint4 t001 = __ldg(b3 + 25);
            uint4 t010 = __ldg(b3 + 2000);
            uint4 t011 = __ldg(b3 + 2025);
            uint4 t100 = __ldg(b3 + 120000);
            uint4 t101 = __ldg(b3 + 120025);
            uint4 t110 = __ldg(b3 + 122000);
            uint4 t111 = __ldg(b3 + 122025);
            uint4 u00  = __ldg(b2);
            uint4 u01  = __ldg(b2 + 25);
            uint4 u10  = __ldg(b2 + 4000);
            uint4 u11  = __ldg(b2 + 4025);

            float wx0 = 1.f - fx, wy0 = 1.f - fy, wz0 = 1.f - fz;
            float wu0 = 1.f - fu, wv0 = 1.f - fv;
            float wzy00 = wz0 * wy0, wzy01 = wz0 * fy;
            float wzy10 = fz * wy0,  wzy11 = fz * fy;

            uint64_t acc[4] = {0, 0, 0, 0};
            fma_tap(acc, t000, pack2(wzy00 * wx0));
            fma_tap(acc, t001, pack2(wzy00 * fx));
            fma_tap(acc, t010, pack2(wzy01 * wx0));
            fma_tap(acc, t011, pack2(wzy01 * fx));
            fma_tap(acc, t100, pack2(wzy10 * wx0));
            fma_tap(acc, t101, pack2(wzy10 * fx));
            fma_tap(acc, t110, pack2(wzy11 * wx0));
            fma_tap(acc, t111, pack2(wzy11 * fx));
            fma_tap(acc, u00,  pack2(wv0 * wu0));
            fma_tap(acc, u01,  pack2(wv0 * fu));
            fma_tap(acc, u10,  pack2(fv * wu0));
            fma_tap(acc, u11,  pack2(fv * fu));

            // channel ch = lane*8 + j stored at column (lane + 25*j):
            // lanes map to consecutive banks -> conflict-free STS.
            float* srow = &stage[z * 209];
            #pragma unroll
            for (int q = 0; q < 4; q++) {
                float lo, hi;
                asm("mov.b64 {%0, %1}, %2;" : "=f"(lo), "=f"(hi) : "l"(acc[q]));
                srow[lane + 25 * (2 * q)]     = lo;
                srow[lane + 25 * (2 * q + 1)] = hi;
            }
        }
    }
    __syncthreads();

    // out[b][c][x][y][z] = ((bb*200+c)*129600) + x*2160 + y*60 + z
    const size_t obase = (size_t)bb * Cn * (size_t)NV
                       + (size_t)xx * (SY * SZ) + (size_t)yy * SZ;
    for (int e = tid; e < 60 * Cn; e += 256) {
        int ch = e / 60;
        int z  = e - ch * 60;
        int col = (ch >> 3) + 25 * (ch & 7);
        out[obase + (size_t)ch * NV + z] = stage[z * 209 + col];
    }
}

// ---------------------------------------------------------------------------
extern "C" void kernel_launch(void* const* d_in, const int* in_sizes, int n_in,
                              void* d_out, int out_size)
{
    // Classify inputs by element count (sums commutative -> order within a
    // same-size pair is irrelevant).
    const float *x3a = nullptr, *x3b = nullptr;
    const float *x2a = nullptr, *x2b = nullptr;
    const float *pp  = nullptr;
    for (int i = 0; i < n_in; i++) {
        const float* ptr = (const float*)d_in[i];
        if (in_sizes[i] == Bn * Cn * CELL3) {          // 30,720,000
            if (!x3a) x3a = ptr; else x3b = ptr;
        } else if (in_sizes[i] == Bn * Cn * CELL2) {   // 7,680,000
            if (!x2a) x2a = ptr; else x2b = ptr;
        } else if (in_sizes[i] == Bn * NV * 3) {       // 777,600
            pp = ptr;
        }
    }

    transpose_sum_kernel<<<dim3(T3 + T2, Bn), 256>>>(
        (const float4*)x3a, (const float4*)x3b,
        (const float4*)x2a, (const float4*)x2b);
    flosp_kernel<<<dim3(SX * SY, Bn), 256>>>(pp, (float*)d_out);
}

// round 6
// speedup vs baseline: 1.3611x; 1.3611x over previous
#include <cuda_runtime.h>
#include <cuda_fp16.h>
#include <cstdint>

// Problem constants
constexpr int Bn   = 2;      // batch
constexpr int Cn   = 200;    // channels
constexpr int D3   = 16, H3 = 60, W3 = 80;     // 3D volume dims
constexpr int H2   = 120, W2 = 160;            // 2D image dims
constexpr int SX   = 60, SY = 36, SZ = 60;     // scene
constexpr int NV   = SX * SY * SZ;             // 129600 voxels per batch
constexpr int CELL3 = D3 * H3 * W3;            // 76800
constexpr int CELL2 = H2 * W2;                 // 19200
constexpr int T3   = CELL3 / 128;              // 600 transpose tiles (3D)
constexpr int T2   = CELL2 / 128;              // 150 transpose tiles (2D)

// Scratch: channel-last, pre-summed, fp16, packed 400B rows (all 200 ch).
__device__ __half S3h[(size_t)Bn * CELL3 * Cn];   // 61.4 MB
__device__ __half S2h[(size_t)Bn * CELL2 * Cn];   // 15.4 MB

// ---------------------------------------------------------------------------
// Pass 1 (fused 3D+2D): sum a+b, fp16-convert, transpose channels innermost.
// ---------------------------------------------------------------------------
__global__ void __launch_bounds__(256) transpose_sum_kernel(
    const float4* __restrict__ x3a, const float4* __restrict__ x3b,
    const float4* __restrict__ x2a, const float4* __restrict__ x2b)
{
    __shared__ uint16_t tile[128][210];
    const int bx   = blockIdx.x;
    const int bb   = blockIdx.y;
    const int lane = threadIdx.x & 31;
    const int w    = threadIdx.x >> 5;    // 8 warps

    const float4 *a, *b;
    __half* dst;
    int ncell, cell0;
    if (bx < T3) { a = x3a; b = x3b; dst = S3h; ncell = CELL3; cell0 = bx * 128; }
    else         { a = x2a; b = x2b; dst = S2h; ncell = CELL2; cell0 = (bx - T3) * 128; }

    const size_t cq   = (size_t)(ncell / 4);
    const size_t base = (size_t)bb * Cn * cq + (size_t)(cell0 / 4) + lane;

    for (int c = w; c < Cn; c += 8) {
        size_t ia = base + (size_t)c * cq;
        float4 va = __ldg(a + ia);
        float4 vb = __ldg(b + ia);
        int cell = lane * 4;
        tile[cell + 0][c] = __half_as_ushort(__float2half_rn(va.x + vb.x));
        tile[cell + 1][c] = __half_as_ushort(__float2half_rn(va.y + vb.y));
        tile[cell + 2][c] = __half_as_ushort(__float2half_rn(va.z + vb.z));
        tile[cell + 3][c] = __half_as_ushort(__float2half_rn(va.w + vb.w));
    }
    __syncthreads();

    const uint32_t* t32 = reinterpret_cast<const uint32_t*>(&tile[0][0]); // row = 105 words
    __half* outp = dst + ((size_t)bb * ncell + cell0) * Cn;
    for (int e = threadIdx.x; e < 128 * 50; e += 256) {
        int cell = e / 50;
        int q    = e - cell * 50;
        uint2 v;
        v.x = t32[cell * 105 + 2 * q];
        v.y = t32[cell * 105 + 2 * q + 1];
        *reinterpret_cast<uint2*>(outp + (size_t)cell * Cn + 4 * q) = v;
    }
}

// ---------------------------------------------------------------------------
// Pass 2: gather. One warp per voxel, 25 active lanes x uint4 (8 fp16 ch).
// x/y (3D) and u/v (2D) lerps in fp16 (HFMA2); z-lerp + cross-source add in
// fp32 (f32x2). Stage fp16 in smem; tail converts + writes z-contiguous.
// ---------------------------------------------------------------------------
__device__ __forceinline__ uint4 h2lerp4(uint4 a, uint4 b, __half2 t) {
    const __half2* A = reinterpret_cast<const __half2*>(&a);
    const __half2* B = reinterpret_cast<const __half2*>(&b);
    uint4 r;
    __half2* R = reinterpret_cast<__half2*>(&r);
#pragma unroll
    for (int k = 0; k < 4; k++)
        R[k] = __hfma2(__hsub2(B[k], A[k]), t, A[k]);
    return r;
}
__device__ __forceinline__ uint64_t pack2(float v) {
    uint64_t r;
    asm("mov.b64 %0, {%1, %1};" : "=l"(r) : "f"(v));
    return r;
}
__device__ __forceinline__ uint64_t packf2(float2 f) {
    uint64_t r;
    asm("mov.b64 %0, {%1, %2};" : "=l"(r) : "f"(f.x), "f"(f.y));
    return r;
}
__device__ __forceinline__ void fma2(uint64_t& acc, uint64_t a, uint64_t w) {
    asm("fma.rn.f32x2 %0, %1, %2, %0;" : "+l"(acc) : "l"(a), "l"(w));
}
__device__ __forceinline__ uint32_t f2_to_h2(uint64_t acc) {
    float lo, hi;
    asm("mov.b64 {%0, %1}, %2;" : "=f"(lo), "=f"(hi) : "l"(acc));
    uint32_t r;
    asm("cvt.rn.f16x2.f32 %0, %1, %2;" : "=r"(r) : "f"(hi), "f"(lo));
    return r;
}

__global__ void __launch_bounds__(256, 5) flosp_kernel(
    const float* __restrict__ pp, float* __restrict__ out)
{
    // stage[z][p]: half2 word for channel pair p (p = lane + 25k -> ch pair)
    __shared__ uint32_t stage[60][101];   // 24.2 KB, odd stride
    const int tid  = threadIdx.x;
    const int lane = tid & 31;
    const int w    = tid >> 5;            // 8 warps
    const int yy   = blockIdx.x % SY;
    const int xx   = blockIdx.x / SY;
    const int bb   = blockIdx.y;

    const uint4* __restrict__ s3 =
        reinterpret_cast<const uint4*>(S3h) + (size_t)bb * CELL3 * 25;
    const uint4* __restrict__ s2 =
        reinterpret_cast<const uint4*>(S2h) + (size_t)bb * CELL2 * 25;
    const float* pprow = pp + (size_t)bb * NV * 3;
    const bool active = lane < 25;

    for (int i = 0; i < 8; i++) {
        int z = w * 8 + i;
        if (z >= 60) break;
        int vox = (xx * SZ + z) * SY + yy;
        const float* p = pprow + (size_t)vox * 3;
        float p0 = __ldg(p + 0), p1 = __ldg(p + 1), p2 = __ldg(p + 2);

        // 3D coords (grid in [-1,1) -> all taps in-bounds; clamp == ref mask)
        float gx = (p0 + 1.f) * (0.5f * (W3 - 1));
        float gy = (p1 + 1.f) * (0.5f * (H3 - 1));
        float gz = (p2 + 1.f) * (0.5f * (D3 - 1));
        int ix = min(max((int)floorf(gx), 0), W3 - 2);
        int iy = min(max((int)floorf(gy), 0), H3 - 2);
        int iz = min(max((int)floorf(gz), 0), D3 - 2);
        float fx = gx - (float)ix, fy = gy - (float)iy, fz = gz - (float)iz;
        // 2D coords
        float gu = (p0 + 1.f) * (0.5f * (W2 - 1));
        float gv = (p1 + 1.f) * (0.5f * (H2 - 1));
        int iu = min(max((int)floorf(gu), 0), W2 - 2);
        int iv = min(max((int)floorf(gv), 0), H2 - 2);
        float fu = gu - (float)iu, fv = gv - (float)iv;

        if (active) {
            __half2 fx2 = __float2half2_rn(fx);
            __half2 fy2 = __float2half2_rn(fy);
            __half2 fu2 = __float2half2_rn(fu);
            __half2 fv2 = __float2half2_rn(fv);
            uint64_t wz0_2 = pack2(1.f - fz);
            uint64_t wz1_2 = pack2(fz);

            // strides in uint4 units (row = 25 uint4 = 400B):
            // 3D: dx=25, dy=2000, dz=120000; 2D: du=25, dv=4000
            const uint4* b3 = s3 + (size_t)((iz * H3 + iy) * W3 + ix) * 25 + lane;
            const uint4* b2 = s2 + (size_t)(iv * W2 + iu) * 25 + lane;

            uint4 t000 = __ldg(b3);
            uint4 t001 = __ldg(b3 + 25);
            uint4 t010 = __ldg(b3 + 2000);
            uint4 t011 = __ldg(b3 + 2025);
            uint4 t100 = __ldg(b3 + 120000);
            uint4 t101 = __ldg(b3 + 120025);
            uint4 t110 = __ldg(b3 + 122000);
            uint4 t111 = __ldg(b3 + 122025);
            uint4 u00  = __ldg(b2);
            uint4 u01  = __ldg(b2 + 25);
            uint4 u10  = __ldg(b2 + 4000);
            uint4 u11  = __ldg(b2 + 4025);

            // fp16 lerp tree (x then y); z + cross-source add in fp32
            uint4 c00 = h2lerp4(t000, t001, fx2);
            uint4 c01 = h2lerp4(t010, t011, fx2);
            uint4 c10 = h2lerp4(t100, t101, fx2);
            uint4 c11 = h2lerp4(t110, t111, fx2);
            uint4 cz0 = h2lerp4(c00, c01, fy2);
            uint4 cz1 = h2lerp4(c10, c11, fy2);

            uint4 d0  = h2lerp4(u00, u01, fu2);
            uint4 d1  = h2lerp4(u10, u11, fu2);
            uint4 dd  = h2lerp4(d0, d1, fv2);

            const __half2* Z0 = reinterpret_cast<const __half2*>(&cz0);
            const __half2* Z1 = reinterpret_cast<const __half2*>(&cz1);
            const __half2* DD = reinterpret_cast<const __half2*>(&dd);
            uint32_t* srow = &stage[z][0];
#pragma unroll
            for (int k = 0; k < 4; k++) {
                uint64_t acc = packf2(__half22float2(DD[k]));
                fma2(acc, packf2(__half22float2(Z0[k])), wz0_2);
                fma2(acc, packf2(__half22float2(Z1[k])), wz1_2);
                srow[lane + 25 * k] = f2_to_h2(acc);
            }
        }
    }
    __syncthreads();

    // Tail: stage[z][p] (half2, p -> ch pair (p%25)*8 + (p/25)*2) -> fp32 out,
    // z-contiguous STG.128. out[b][c][x][y][z].
    const size_t obase = (size_t)bb * Cn * (size_t)NV
                       + (size_t)xx * (SY * SZ) + (size_t)yy * SZ;
    // 100 pairs x 15 z-quads = 1500 chunks
    for (int t = tid; t < 1500; t += 256) {
        int pcol = t / 15;
        int z0   = (t - pcol * 15) * 4;
        int ch_lo = (pcol % 25) * 8 + (pcol / 25) * 2;
        uint32_t w0 = stage[z0 + 0][pcol];
        uint32_t w1 = stage[z0 + 1][pcol];
        uint32_t w2 = stage[z0 + 2][pcol];
        uint32_t w3 = stage[z0 + 3][pcol];
        float2 f0 = __half22float2(*reinterpret_cast<__half2*>(&w0));
        float2 f1 = __half22float2(*reinterpret_cast<__half2*>(&w1));
        float2 f2 = __half22float2(*reinterpret_cast<__half2*>(&w2));
        float2 f3 = __half22float2(*reinterpret_cast<__half2*>(&w3));
        float4 lo = make_float4(f0.x, f1.x, f2.x, f3.x);
        float4 hi = make_float4(f0.y, f1.y, f2.y, f3.y);
        *reinterpret_cast<float4*>(out + obase + (size_t)ch_lo * NV + z0)       = lo;
        *reinterpret_cast<float4*>(out + obase + (size_t)(ch_lo + 1) * NV + z0) = hi;
    }
}

// ---------------------------------------------------------------------------
extern "C" void kernel_launch(void* const* d_in, const int* in_sizes, int n_in,
                              void* d_out, int out_size)
{
    const float *x3a = nullptr, *x3b = nullptr;
    const float *x2a = nullptr, *x2b = nullptr;
    const float *pp  = nullptr;
    for (int i = 0; i < n_in; i++) {
        const float* ptr = (const float*)d_in[i];
        if (in_sizes[i] == Bn * Cn * CELL3) {          // 30,720,000
            if (!x3a) x3a = ptr; else x3b = ptr;
        } else if (in_sizes[i] == Bn * Cn * CELL2) {   // 7,680,000
            if (!x2a) x2a = ptr; else x2b = ptr;
        } else if (in_sizes[i] == Bn * NV * 3) {       // 777,600
            pp = ptr;
        }
    }

    transpose_sum_kernel<<<dim3(T3 + T2, Bn), 256>>>(
        (const float4*)x3a, (const float4*)x3b,
        (const float4*)x2a, (const float4*)x2b);
    flosp_kernel<<<dim3(SX * SY, Bn), 256>>>(pp, (float*)d_out);
}

// round 13
// speedup vs baseline: 1.3738x; 1.0093x over previous
#include <cuda_runtime.h>
#include <cuda_fp16.h>
#include <cstdint>

// Problem constants
constexpr int Bn   = 2;      // batch
constexpr int Cn   = 200;    // channels
constexpr int D3   = 16, H3 = 60, W3 = 80;     // 3D volume dims
constexpr int H2   = 120, W2 = 160;            // 2D image dims
constexpr int SX   = 60, SY = 36, SZ = 60;     // scene
constexpr int NV   = SX * SY * SZ;             // 129600 voxels per batch
constexpr int CELL3 = D3 * H3 * W3;            // 76800
constexpr int CELL2 = H2 * W2;                 // 19200
constexpr int T3   = CELL3 / 128;              // 600 transpose tiles (3D)
constexpr int T2   = CELL2 / 128;              // 150 transpose tiles (2D)

// Scratch: channel-last, pre-summed, fp16, packed 400B rows (all 200 ch).
__device__ __half S3h[(size_t)Bn * CELL3 * Cn];   // 61.4 MB
__device__ __half S2h[(size_t)Bn * CELL2 * Cn];   // 15.4 MB

__device__ __forceinline__ uint32_t h2_bits(__half2 h) {
    return *reinterpret_cast<uint32_t*>(&h);      // pure bit-cast, no SASS
}

// ---------------------------------------------------------------------------
// Pass 1 (fused 3D+2D): sum a+b, fp16-convert, transpose channels innermost.
// Channel-PAIR per thread: 4 LDG.128, pack half2, 4 STS.32 into a pow2-row
// XOR-swizzled tile (conflict-free stores). 64KB dynamic smem.
// ---------------------------------------------------------------------------
__global__ void __launch_bounds__(256) transpose_sum_kernel(
    const float4* __restrict__ x3a, const float4* __restrict__ x3b,
    const float4* __restrict__ x2a, const float4* __restrict__ x2b)
{
    extern __shared__ uint32_t tile[];    // [128 cells][128 words] = 64KB
    const int bx   = blockIdx.x;
    const int bb   = blockIdx.y;
    const int lane = threadIdx.x & 31;
    const int w    = threadIdx.x >> 5;    // 8 warps

    const float4 *a, *b;
    __half* dst;
    int ncell, cell0;
    if (bx < T3) { a = x3a; b = x3b; dst = S3h; ncell = CELL3; cell0 = bx * 128; }
    else         { a = x2a; b = x2b; dst = S2h; ncell = CELL2; cell0 = (bx - T3) * 128; }

    const size_t cq   = (size_t)(ncell / 4);
    const size_t base = (size_t)bb * Cn * cq + (size_t)(cell0 / 4) + lane;

    // cp = channel pair index (ch 2cp, 2cp+1); word = half2(ch_lo, ch_hi)
    for (int cp = w; cp < 100; cp += 8) {
        size_t ia0 = base + (size_t)(2 * cp) * cq;
        size_t ia1 = ia0 + cq;
        float4 a0 = __ldg(a + ia0), b0 = __ldg(b + ia0);
        float4 a1 = __ldg(a + ia1), b1 = __ldg(b + ia1);
        const int cell = lane * 4;
        const int swc  = cp ^ lane;       // ((cell+j)>>2)&31 == lane for j<4
        tile[(cell + 0) * 128 + swc] =
            h2_bits(__floats2half2_rn(a0.x + b0.x, a1.x + b1.x));
        tile[(cell + 1) * 128 + swc] =
            h2_bits(__floats2half2_rn(a0.y + b0.y, a1.y + b1.y));
        tile[(cell + 2) * 128 + swc] =
            h2_bits(__floats2half2_rn(a0.z + b0.z, a1.z + b1.z));
        tile[(cell + 3) * 128 + swc] =
            h2_bits(__floats2half2_rn(a0.w + b0.w, a1.w + b1.w));
    }
    __syncthreads();

    __half* outp = dst + ((size_t)bb * ncell + cell0) * Cn;
    for (int e = threadIdx.x; e < 128 * 50; e += 256) {
        int cell = e / 50;
        int q    = e - cell * 50;         // uint2 = channels 4q..4q+3
        int s    = cell >> 2;
        uint2 v;
        v.x = tile[cell * 128 + ((2 * q) ^ s)];
        v.y = tile[cell * 128 + ((2 * q + 1) ^ s)];
        *reinterpret_cast<uint2*>(outp + (size_t)cell * Cn + 4 * q) = v;
    }
}

// ---------------------------------------------------------------------------
// Pass 2: gather. One warp per voxel, 25 active lanes x uint4 (8 fp16 ch).
// x/y (3D) and u/v (2D) lerps in fp16 (HFMA2); z-lerp + cross-source add in
// fp32 (f32x2). Stage fp16 in smem as stage[pcol][zp], zp z-interleaved so
// both STS (stride 61) and tail LDS (stride 1) are conflict-free while STG
// stays z-contiguous.
// ---------------------------------------------------------------------------
__device__ __forceinline__ uint4 h2lerp4(uint4 a, uint4 b, __half2 t) {
    const __half2* A = reinterpret_cast<const __half2*>(&a);
    const __half2* B = reinterpret_cast<const __half2*>(&b);
    uint4 r;
    __half2* R = reinterpret_cast<__half2*>(&r);
#pragma unroll
    for (int k = 0; k < 4; k++)
        R[k] = __hfma2(__hsub2(B[k], A[k]), t, A[k]);
    return r;
}
__device__ __forceinline__ uint64_t pack2(float v) {
    uint64_t r;
    asm("mov.b64 %0, {%1, %1};" : "=l"(r) : "f"(v));
    return r;
}
__device__ __forceinline__ uint64_t packf2(float2 f) {
    uint64_t r;
    asm("mov.b64 %0, {%1, %2};" : "=l"(r) : "f"(f.x), "f"(f.y));
    return r;
}
__device__ __forceinline__ void fma2(uint64_t& acc, uint64_t a, uint64_t w) {
    asm("fma.rn.f32x2 %0, %1, %2, %0;" : "+l"(acc) : "l"(a), "l"(w));
}
__device__ __forceinline__ uint32_t f2_to_h2(uint64_t acc) {
    float lo, hi;
    asm("mov.b64 {%0, %1}, %2;" : "=f"(lo), "=f"(hi) : "l"(acc));
    uint32_t r;
    asm("cvt.rn.f16x2.f32 %0, %1, %2;" : "=r"(r) : "f"(hi), "f"(lo));
    return r;
}

__global__ void __launch_bounds__(256, 5) flosp_kernel(
    const float* __restrict__ pp, float* __restrict__ out)
{
    // stage[pcol][zp]: pcol = lane + 25k (ch pair), zp = (z&3)*15 + (z>>2)
    __shared__ uint32_t stage[100][61];   // 24.4 KB
    const int tid  = threadIdx.x;
    const int lane = tid & 31;
    const int w    = tid >> 5;            // 8 warps
    const int yy   = blockIdx.x % SY;
    const int xx   = blockIdx.x / SY;
    const int bb   = blockIdx.y;

    const uint4* __restrict__ s3 =
        reinterpret_cast<const uint4*>(S3h) + (size_t)bb * CELL3 * 25;
    const uint4* __restrict__ s2 =
        reinterpret_cast<const uint4*>(S2h) + (size_t)bb * CELL2 * 25;
    const float* pprow = pp + (size_t)bb * NV * 3;
    const bool active = lane < 25;

    for (int i = 0; i < 8; i++) {
        int z = w * 8 + i;
        if (z >= 60) break;
        int vox = (xx * SZ + z) * SY + yy;
        const float* p = pprow + (size_t)vox * 3;
        float p0 = __ldg(p + 0), p1 = __ldg(p + 1), p2 = __ldg(p + 2);

        // 3D coords (grid in [-1,1) -> all taps in-bounds; clamp == ref mask)
        float gx = (p0 + 1.f) * (0.5f * (W3 - 1));
        float gy = (p1 + 1.f) * (0.5f * (H3 - 1));
        float gz = (p2 + 1.f) * (0.5f * (D3 - 1));
        int ix = min(max((int)floorf(gx), 0), W3 - 2);
        int iy = min(max((int)floorf(gy), 0), H3 - 2);
        int iz = min(max((int)floorf(gz), 0), D3 - 2);
        float fx = gx - (float)ix, fy = gy - (float)iy, fz = gz - (float)iz;
        // 2D coords
        float gu = (p0 + 1.f) * (0.5f * (W2 - 1));
        float gv = (p1 + 1.f) * (0.5f * (H2 - 1));
        int iu = min(max((int)floorf(gu), 0), W2 - 2);
        int iv = min(max((int)floorf(gv), 0), H2 - 2);
        float fu = gu - (float)iu, fv = gv - (float)iv;

        if (active) {
            __half2 fx2 = __float2half2_rn(fx);
            __half2 fy2 = __float2half2_rn(fy);
            __half2 fu2 = __float2half2_rn(fu);
            __half2 fv2 = __float2half2_rn(fv);
            uint64_t wz0_2 = pack2(1.f - fz);
            uint64_t wz1_2 = pack2(fz);

            // strides in uint4 units (row = 25 uint4 = 400B):
            // 3D: dx=25, dy=2000, dz=120000; 2D: du=25, dv=4000
            const uint4* b3 = s3 + (size_t)((iz * H3 + iy) * W3 + ix) * 25 + lane;
            const uint4* b2 = s2 + (size_t)(iv * W2 + iu) * 25 + lane;

            uint4 t000 = __ldg(b3);
            uint4 t001 = __ldg(b3 + 25);
            uint4 t010 = __ldg(b3 + 2000);
            uint4 t011 = __ldg(b3 + 2025);
            uint4 t100 = __ldg(b3 + 120000);
            uint4 t101 = __ldg(b3 + 120025);
            uint4 t110 = __ldg(b3 + 122000);
            uint4 t111 = __ldg(b3 + 122025);
            uint4 u00  = __ldg(b2);
            uint4 u01  = __ldg(b2 + 25);
            uint4 u10  = __ldg(b2 + 4000);
            uint4 u11  = __ldg(b2 + 4025);

            // fp16 lerp tree (x then y); z + cross-source add in fp32
            uint4 c00 = h2lerp4(t000, t001, fx2);
            uint4 c01 = h2lerp4(t010, t011, fx2);
            uint4 c10 = h2lerp4(t100, t101, fx2);
            uint4 c11 = h2lerp4(t110, t111, fx2);
            uint4 cz0 = h2lerp4(c00, c01, fy2);
            uint4 cz1 = h2lerp4(c10, c11, fy2);

            uint4 d0  = h2lerp4(u00, u01, fu2);
            uint4 d1  = h2lerp4(u10, u11, fu2);
            uint4 dd  = h2lerp4(d0, d1, fv2);

            const __half2* Z0 = reinterpret_cast<const __half2*>(&cz0);
            const __half2* Z1 = reinterpret_cast<const __half2*>(&cz1);
            const __half2* DD = reinterpret_cast<const __half2*>(&dd);
            const int zp = (z & 3) * 15 + (z >> 2);
#pragma unroll
            for (int k = 0; k < 4; k++) {
                uint64_t acc = packf2(__half22float2(DD[k]));
                fma2(acc, packf2(__half22float2(Z0[k])), wz0_2);
                fma2(acc, packf2(__half22float2(Z1[k])), wz1_2);
                stage[lane + 25 * k][zp] = f2_to_h2(acc);   // stride 61: conflict-free
            }
        }
    }
    __syncthreads();

    // Tail: per chunk, one ch-pair (pcol) x one z-quad (z0=4m). LDS stride-1
    // (conflict-free), STG.128 z-contiguous.
    const size_t obase = (size_t)bb * Cn * (size_t)NV
                       + (size_t)xx * (SY * SZ) + (size_t)yy * SZ;
    for (int t = tid; t < 1500; t += 256) {
        int pcol = t / 15;
        int m    = t - pcol * 15;
        int z0   = 4 * m;
        int ch_lo = (pcol % 25) * 8 + (pcol / 25) * 2;
        uint32_t w0 = stage[pcol][m];        // z0+0
        uint32_t w1 = stage[pcol][m + 15];   // z0+1
        uint32_t w2 = stage[pcol][m + 30];   // z0+2
        uint32_t w3 = stage[pcol][m + 45];   // z0+3
        float2 f0 = __half22float2(*reinterpret_cast<__half2*>(&w0));
        float2 f1 = __half22float2(*reinterpret_cast<__half2*>(&w1));
        float2 f2 = __half22float2(*reinterpret_cast<__half2*>(&w2));
        float2 f3 = __half22float2(*reinterpret_cast<__half2*>(&w3));
        float4 lo = make_float4(f0.x, f1.x, f2.x, f3.x);
        float4 hi = make_float4(f0.y, f1.y, f2.y, f3.y);
        *reinterpret_cast<float4*>(out + obase + (size_t)ch_lo * NV + z0)       = lo;
        *reinterpret_cast<float4*>(out + obase + (size_t)(ch_lo + 1) * NV + z0) = hi;
    }
}

// ---------------------------------------------------------------------------
extern "C" void kernel_launch(void* const* d_in, const int* in_sizes, int n_in,
                              void* d_out, int out_size)
{
    const float *x3a = nullptr, *x3b = nullptr;
    const float *x2a = nullptr, *x2b = nullptr;
    const float *pp  = nullptr;
    for (int i = 0; i < n_in; i++) {
        const float* ptr = (const float*)d_in[i];
        if (in_sizes[i] == Bn * Cn * CELL3) {          // 30,720,000
            if (!x3a) x3a = ptr; else x3b = ptr;
        } else if (in_sizes[i] == Bn * Cn * CELL2) {   // 7,680,000
            if (!x2a) x2a = ptr; else x2b = ptr;
        } else if (in_sizes[i] == Bn * NV * 3) {       // 777,600
            pp = ptr;
        }
    }

    cudaFuncSetAttribute(transpose_sum_kernel,
                         cudaFuncAttributeMaxDynamicSharedMemorySize, 65536);
    transpose_sum_kernel<<<dim3(T3 + T2, Bn), 256, 65536>>>(
        (const float4*)x3a, (const float4*)x3b,
        (const float4*)x2a, (const float4*)x2b);
    flosp_kernel<<<dim3(SX * SY, Bn), 256>>>(pp, (float*)d_out);
}